// round 1
// baseline (speedup 1.0000x reference)
#include <cuda_runtime.h>

// Noisy LIF spiking neuron scan.
// x, noise: [B, T, N] fp32 ; out: [B, T, N] fp32 (0/1 spikes)
// Recurrence over t per (b, n) lane:
//   u = 0.5*u + x[b,t,n] - 0.5*noise[b,t,n]
//   o = (u - 1 > 0) ? 1 : 0
//   u = u * (1 - o)
//
// Pure HBM streaming: 768 MB total traffic. One thread owns 4 adjacent
// lanes (float4) for 128-bit coalesced transactions and 4 independent
// dependency chains. T unrolled fully so loads are issued ahead of the
// short FMA chain.

static constexpr int B = 16;
static constexpr int T = 64;
static constexpr int N = 65536;
static constexpr int N4 = N / 4;          // float4 lanes per (b, t) row

__global__ __launch_bounds__(256) void lif_kernel(
    const float4* __restrict__ x,
    const float4* __restrict__ noise,
    float4* __restrict__ out)
{
    int idx = blockIdx.x * blockDim.x + threadIdx.x;   // 0 .. B*N4-1
    if (idx >= B * N4) return;

    int b  = idx / N4;
    int n4 = idx % N4;

    const float4* __restrict__ xp = x     + (size_t)b * T * N4 + n4;
    const float4* __restrict__ np = noise + (size_t)b * T * N4 + n4;
    float4*       __restrict__ op = out   + (size_t)b * T * N4 + n4;

    float ux = 0.f, uy = 0.f, uz = 0.f, uw = 0.f;

#pragma unroll
    for (int t = 0; t < T; t++) {
        const float4 xv = __ldcs(xp + t * N4);
        const float4 nv = __ldcs(np + t * N4);

        float4 o;

        ux = fmaf(0.5f, ux, xv.x) - 0.5f * nv.x;
        o.x = (ux > 1.0f) ? 1.0f : 0.0f;
        ux = (ux > 1.0f) ? 0.0f : ux;

        uy = fmaf(0.5f, uy, xv.y) - 0.5f * nv.y;
        o.y = (uy > 1.0f) ? 1.0f : 0.0f;
        uy = (uy > 1.0f) ? 0.0f : uy;

        uz = fmaf(0.5f, uz, xv.z) - 0.5f * nv.z;
        o.z = (uz > 1.0f) ? 1.0f : 0.0f;
        uz = (uz > 1.0f) ? 0.0f : uz;

        uw = fmaf(0.5f, uw, xv.w) - 0.5f * nv.w;
        o.w = (uw > 1.0f) ? 1.0f : 0.0f;
        uw = (uw > 1.0f) ? 0.0f : uw;

        __stcs(op + t * N4, o);
    }
}

extern "C" void kernel_launch(void* const* d_in, const int* in_sizes, int n_in,
                              void* d_out, int out_size)
{
    const float4* x     = (const float4*)d_in[0];
    const float4* noise = (const float4*)d_in[1];
    float4*       out   = (float4*)d_out;

    const int total_threads = B * N4;        // 262144
    const int tpb = 256;
    const int blocks = (total_threads + tpb - 1) / tpb;   // 1024

    lif_kernel<<<blocks, tpb>>>(x, noise, out);
}

// round 2
// speedup vs baseline: 1.0329x; 1.0329x over previous
#include <cuda_runtime.h>

// Noisy LIF spiking neuron scan — R2: batched-load MLP + finer CTA granularity.
// x, noise: [B, T, N] fp32 ; out: [B, T, N] fp32 (0/1 spikes)
//   u = 0.5*u + x[t] - 0.5*noise[t] ; o = (u > 1) ; u = o ? 0 : u
//
// 768 MB irreducible HBM traffic. One thread owns 4 adjacent lanes (float4).
// T processed in chunks of CH=4: all 2*CH LDG.128 issued front-batched so
// each thread keeps 8 loads in flight (ptxas re-rolled the fully-unrolled
// version down to regs=28 / MLP~2 in R1). 128-thread blocks (2048 CTAs)
// reduce the 7-vs-6 CTA/SM wave imbalance seen at 1024 CTAs.

static constexpr int B  = 16;
static constexpr int T  = 64;
static constexpr int N  = 65536;
static constexpr int N4 = N / 4;     // float4 lanes per (b, t) row
static constexpr int CH = 4;         // timesteps per load batch

__global__ __launch_bounds__(128) void lif_kernel(
    const float4* __restrict__ x,
    const float4* __restrict__ noise,
    float4* __restrict__ out)
{
    int idx = blockIdx.x * blockDim.x + threadIdx.x;   // 0 .. B*N4-1
    if (idx >= B * N4) return;

    int b  = idx / N4;
    int n4 = idx % N4;

    const size_t base = (size_t)b * T * N4 + n4;
    const float4* __restrict__ xp = x     + base;
    const float4* __restrict__ np = noise + base;
    float4*       __restrict__ op = out   + base;

    float ux = 0.f, uy = 0.f, uz = 0.f, uw = 0.f;

#pragma unroll
    for (int t0 = 0; t0 < T; t0 += CH) {
        float4 xv[CH], nv[CH];

        // Front-batch all loads for this chunk: 2*CH independent LDG.128.
#pragma unroll
        for (int j = 0; j < CH; j++) {
            xv[j] = __ldcs(xp + (t0 + j) * N4);
            nv[j] = __ldcs(np + (t0 + j) * N4);
        }

#pragma unroll
        for (int j = 0; j < CH; j++) {
            float4 o;

            ux  = fmaf(0.5f, ux, xv[j].x) - 0.5f * nv[j].x;
            o.x = (ux > 1.0f) ? 1.0f : 0.0f;
            ux  = (ux > 1.0f) ? 0.0f : ux;

            uy  = fmaf(0.5f, uy, xv[j].y) - 0.5f * nv[j].y;
            o.y = (uy > 1.0f) ? 1.0f : 0.0f;
            uy  = (uy > 1.0f) ? 0.0f : uy;

            uz  = fmaf(0.5f, uz, xv[j].z) - 0.5f * nv[j].z;
            o.z = (uz > 1.0f) ? 1.0f : 0.0f;
            uz  = (uz > 1.0f) ? 0.0f : uz;

            uw  = fmaf(0.5f, uw, xv[j].w) - 0.5f * nv[j].w;
            o.w = (uw > 1.0f) ? 1.0f : 0.0f;
            uw  = (uw > 1.0f) ? 0.0f : uw;

            __stcs(op + (t0 + j) * N4, o);
        }
    }
}

extern "C" void kernel_launch(void* const* d_in, const int* in_sizes, int n_in,
                              void* d_out, int out_size)
{
    const float4* x     = (const float4*)d_in[0];
    const float4* noise = (const float4*)d_in[1];
    float4*       out   = (float4*)d_out;

    const int total_threads = B * N4;                    // 262144
    const int tpb = 128;
    const int blocks = (total_threads + tpb - 1) / tpb;  // 2048

    lif_kernel<<<blocks, tpb>>>(x, noise, out);
}